// round 12
// baseline (speedup 1.0000x reference)
#include <cuda_runtime.h>
#include <cuda_bf16.h>
#include <math.h>
#include <stdint.h>

#define D_MODEL 1024
#define NHEAD 16
#define HD 64
#define BATCH 8
#define TQ 1024
#define TK 1024

// Scratch (static __device__ arrays; no allocation allowed)
__device__ float g_Q[BATCH * TQ * D_MODEL];
__device__ float g_K[BATCH * TK * D_MODEL];
__device__ float g_V[BATCH * TK * D_MODEL];
__device__ float g_O[BATCH * TQ * D_MODEL];
__device__ float g_L[BATCH * NHEAD * TQ];
__device__ __nv_bfloat16 g_E[BATCH * NHEAD * TQ * TK];   // unnormalized exp(scores)

__device__ __forceinline__ uint32_t cvt_tf32(float f) {
    uint32_t o;
    asm("cvt.rna.tf32.f32 %0, %1;" : "=r"(o) : "f"(f));
    return o;
}
__device__ __forceinline__ float tf32f(float f) {
    return __uint_as_float(cvt_tf32(f));
}

#define MMA_TF32(acc, a0, a1, a2, a3, b0, b1)                                   \
    asm volatile(                                                               \
        "mma.sync.aligned.m16n8k8.row.col.f32.tf32.tf32.f32 "                   \
        "{%0,%1,%2,%3}, {%4,%5,%6,%7}, {%8,%9}, {%0,%1,%2,%3};"                 \
        : "+f"((acc)[0]), "+f"((acc)[1]), "+f"((acc)[2]), "+f"((acc)[3])        \
        : "r"(a0), "r"(a1), "r"(a2), "r"(a3), "r"(b0), "r"(b1))

// ---------------------------------------------------------------------------
// mma.sync tf32 GEMM v2:  C[M,N] = A[M,K] @ W[N,K]^T + bias  (row-major)
// CTA tile 128x128, BK=16, 128 threads (4 warps), warp tile 64x64.
// ---------------------------------------------------------------------------
#define GROW 20
#define GSTG (128 * GROW)
#define GEMM_DSMEM (4 * GSTG * 4)

__global__ __launch_bounds__(128) void gemm_mma_kernel(
    const float* __restrict__ A, const float* __restrict__ W,
    const float* __restrict__ bias, float* __restrict__ C,
    int M, int N, int K)
{
    extern __shared__ float smf[];
    const int t = threadIdx.x;
    const int lane = t & 31, w = t >> 5;
    const int bx = blockIdx.x;
    const int by = blockIdx.y;
    const int wm = (w & 1) * 64;
    const int wn = (w >> 1) * 64;
    const int g = lane >> 2, tg = lane & 3;

    const float* Ag = A + (size_t)(by * 128) * K;
    const float* Wg = W + (size_t)(bx * 128) * K;

    float acc[4][8][4];
#pragma unroll
    for (int mt = 0; mt < 4; ++mt)
#pragma unroll
        for (int nt = 0; nt < 8; ++nt)
#pragma unroll
            for (int r = 0; r < 4; ++r) acc[mt][nt][r] = 0.f;

    float4 ra[4], rw[4];
    const int NIT = K / 16;

#pragma unroll
    for (int i = 0; i < 4; ++i) {
        const int idx = t + 128 * i;
        const int r = idx >> 2, fq = idx & 3;
        ra[i] = *(const float4*)(Ag + (size_t)r * K + fq * 4);
        rw[i] = *(const float4*)(Wg + (size_t)r * K + fq * 4);
    }
#pragma unroll
    for (int i = 0; i < 4; ++i) {
        const int idx = t + 128 * i;
        const int r = idx >> 2, fq = idx & 3;
        float4 pa, pb;
        pa.x = tf32f(ra[i].x); pa.y = tf32f(ra[i].y);
        pa.z = tf32f(ra[i].z); pa.w = tf32f(ra[i].w);
        pb.x = tf32f(rw[i].x); pb.y = tf32f(rw[i].y);
        pb.z = tf32f(rw[i].z); pb.w = tf32f(rw[i].w);
        *(float4*)(smf + r * GROW + fq * 4) = pa;
        *(float4*)(smf + 2 * GSTG + r * GROW + fq * 4) = pb;
    }
    __syncthreads();

    for (int it = 0; it < NIT; ++it) {
        const int s = it & 1;
        if (it + 1 < NIT) {
            const int k0 = (it + 1) * 16;
#pragma unroll
            for (int i = 0; i < 4; ++i) {
                const int idx = t + 128 * i;
                const int r = idx >> 2, fq = idx & 3;
                ra[i] = *(const float4*)(Ag + (size_t)r * K + k0 + fq * 4);
                rw[i] = *(const float4*)(Wg + (size_t)r * K + k0 + fq * 4);
            }
        }
        {
            const float* as = smf + s * GSTG;
            const float* ws = smf + 2 * GSTG + s * GSTG;
#pragma unroll
            for (int kk = 0; kk < 2; ++kk) {
                const int k0 = kk * 8;
                uint32_t af[4][4];
#pragma unroll
                for (int mt = 0; mt < 4; ++mt) {
                    const int r0 = wm + mt * 16 + g;
                    af[mt][0] = __float_as_uint(as[r0 * GROW + k0 + tg]);
                    af[mt][1] = __float_as_uint(as[(r0 + 8) * GROW + k0 + tg]);
                    af[mt][2] = __float_as_uint(as[r0 * GROW + k0 + 4 + tg]);
                    af[mt][3] = __float_as_uint(as[(r0 + 8) * GROW + k0 + 4 + tg]);
                }
#pragma unroll
                for (int nt = 0; nt < 8; ++nt) {
                    const int c0 = wn + nt * 8 + g;
                    const uint32_t b0 = __float_as_uint(ws[c0 * GROW + k0 + tg]);
                    const uint32_t b1 = __float_as_uint(ws[c0 * GROW + k0 + 4 + tg]);
#pragma unroll
                    for (int mt = 0; mt < 4; ++mt)
                        MMA_TF32(acc[mt][nt], af[mt][0], af[mt][1], af[mt][2],
                                 af[mt][3], b0, b1);
                }
            }
        }
        if (it + 1 < NIT) {
            float* as = smf + (s ^ 1) * GSTG;
            float* ws = smf + 2 * GSTG + (s ^ 1) * GSTG;
#pragma unroll
            for (int i = 0; i < 4; ++i) {
                const int idx = t + 128 * i;
                const int r = idx >> 2, fq = idx & 3;
                float4 pa, pb;
                pa.x = tf32f(ra[i].x); pa.y = tf32f(ra[i].y);
                pa.z = tf32f(ra[i].z); pa.w = tf32f(ra[i].w);
                pb.x = tf32f(rw[i].x); pb.y = tf32f(rw[i].y);
                pb.z = tf32f(rw[i].z); pb.w = tf32f(rw[i].w);
                *(float4*)(as + r * GROW + fq * 4) = pa;
                *(float4*)(ws + r * GROW + fq * 4) = pb;
            }
        }
        __syncthreads();
    }

#pragma unroll
    for (int mt = 0; mt < 4; ++mt) {
        const int row0 = by * 128 + wm + mt * 16 + g;
#pragma unroll
        for (int nt = 0; nt < 8; ++nt) {
            const int col = bx * 128 + wn + nt * 8 + 2 * tg;
            const float2 b01 = *(const float2*)(bias + col);
            float2 v0, v1;
            v0.x = acc[mt][nt][0] + b01.x;
            v0.y = acc[mt][nt][1] + b01.y;
            v1.x = acc[mt][nt][2] + b01.x;
            v1.y = acc[mt][nt][3] + b01.y;
            *(float2*)(C + (size_t)row0 * N + col) = v0;
            *(float2*)(C + (size_t)(row0 + 8) * N + col) = v1;
        }
    }
}

// ---------------------------------------------------------------------------
// Flash-style attention on mma.sync tf32 (v3).
// CTA = (qtile 128, head, batch), 256 threads = 8 warps; warp owns 16 q rows.
// No P smem buffer: exp(S) is converted from mma D-layout to A-fragments
// in registers via 4-lane shfl permutation. V staged transposed (Vt[dv][k],
// stride 68 -> conflict-free B-frag loads). E written to gmem from regs.
// ---------------------------------------------------------------------------
#define ATTN3_SMEM_FLOATS (128 * 68 + 64 * 68 + 64 * 68 + 64 + 128)
#define ATTN3_DSMEM (ATTN3_SMEM_FLOATS * 4)

__global__ __launch_bounds__(256, 3) void attn_mma_kernel(
    const float* __restrict__ coverage, const float* __restrict__ Wcov)
{
    extern __shared__ float sm[];
    float* Qs = sm;                   // [q=128][d stride 68]
    float* Ks = Qs + 128 * 68;        // [key=64][d stride 68]
    float* Vt = Ks + 64 * 68;         // [dv=64][key stride 68]
    float* cb = Vt + 64 * 68;         // [64]
    float* ls = cb + 64;              // [128]

    const int qt = blockIdx.x, h = blockIdx.y, b = blockIdx.z;
    const int tid = threadIdx.x;
    const int lane = tid & 31, w = tid >> 5;
    const int g = lane >> 2, tg = lane & 3;
    const int wq = w * 16;
    const float wch = __ldg(&Wcov[h]);

    // shfl sources for D->A fragment conversion (within 4-lane quad)
    const int src1 = (lane & ~3) + (tg >> 1);
    const int src2 = src1 + 2;
    const bool odd = (tg & 1);

    // Q tile -> smem (tf32)
    {
        const float* Qg = g_Q + ((size_t)(b * TQ + qt * 128)) * D_MODEL + h * HD;
        for (int i = tid; i < 128 * 16; i += 256) {
            int q = i >> 4, d4 = (i & 15) << 2;
            float4 v = *(const float4*)(Qg + (size_t)q * D_MODEL + d4);
            float4 p;
            p.x = tf32f(v.x); p.y = tf32f(v.y); p.z = tf32f(v.z); p.w = tf32f(v.w);
            *(float4*)(Qs + q * 68 + d4) = p;
        }
    }
    if (tid < 128) ls[tid] = 0.f;

    float accO[8][4];
#pragma unroll
    for (int nt = 0; nt < 8; ++nt)
#pragma unroll
        for (int r = 0; r < 4; ++r) accO[nt][r] = 0.f;
    float lp0 = 0.f, lp1 = 0.f;

    __nv_bfloat16* Ebase = g_E + (((size_t)(b * NHEAD + h) * TQ + qt * 128)) * TK;

    for (int kt = 0; kt < 16; ++kt) {
        __syncthreads();   // protect Ks/Vt from previous tile's readers
        const float* Kg = g_K + ((size_t)(b * TK + kt * 64)) * D_MODEL + h * HD;
        const float* Vg = g_V + ((size_t)(b * TK + kt * 64)) * D_MODEL + h * HD;
        for (int i = tid; i < 64 * 16; i += 256) {
            int k = i >> 4, d4 = (i & 15) << 2;
            float4 kv = *(const float4*)(Kg + (size_t)k * D_MODEL + d4);
            float4 pk;
            pk.x = tf32f(kv.x); pk.y = tf32f(kv.y);
            pk.z = tf32f(kv.z); pk.w = tf32f(kv.w);
            *(float4*)(Ks + k * 68 + d4) = pk;
            float4 vv = *(const float4*)(Vg + (size_t)k * D_MODEL + d4);
            Vt[(d4 + 0) * 68 + k] = tf32f(vv.x);
            Vt[(d4 + 1) * 68 + k] = tf32f(vv.y);
            Vt[(d4 + 2) * 68 + k] = tf32f(vv.z);
            Vt[(d4 + 3) * 68 + k] = tf32f(vv.w);
        }
        if (tid < 64) cb[tid] = __ldg(&coverage[b * TK + kt * 64 + tid]) * wch;
        __syncthreads();

        // S = Q K^T : warp rows wq..wq+15, 64 key cols
        float s[8][4];
#pragma unroll
        for (int nt = 0; nt < 8; ++nt)
#pragma unroll
            for (int r = 0; r < 4; ++r) s[nt][r] = 0.f;
#pragma unroll
        for (int kk = 0; kk < 8; ++kk) {
            const int k0 = kk * 8;
            const uint32_t a0 = __float_as_uint(Qs[(wq + g) * 68 + k0 + tg]);
            const uint32_t a1 = __float_as_uint(Qs[(wq + g + 8) * 68 + k0 + tg]);
            const uint32_t a2 = __float_as_uint(Qs[(wq + g) * 68 + k0 + 4 + tg]);
            const uint32_t a3 = __float_as_uint(Qs[(wq + g + 8) * 68 + k0 + 4 + tg]);
#pragma unroll
            for (int nt = 0; nt < 8; ++nt) {
                const uint32_t b0 = __float_as_uint(Ks[(nt * 8 + g) * 68 + k0 + tg]);
                const uint32_t b1 = __float_as_uint(Ks[(nt * 8 + g) * 68 + k0 + 4 + tg]);
                MMA_TF32(s[nt], a0, a1, a2, a3, b0, b1);
            }
        }

        // exp + bias; E store; convert D-layout -> A-fragments in place
        __nv_bfloat16* Eg = Ebase + kt * 64;
#pragma unroll
        for (int nt = 0; nt < 8; ++nt) {
            const int c = nt * 8 + 2 * tg;
            const float cb0 = cb[c], cb1 = cb[c + 1];
            const float e0 = __expf(fmaf(s[nt][0], 0.125f, cb0));
            const float e1 = __expf(fmaf(s[nt][1], 0.125f, cb1));
            const float e2 = __expf(fmaf(s[nt][2], 0.125f, cb0));
            const float e3 = __expf(fmaf(s[nt][3], 0.125f, cb1));
            lp0 += e0 + e1;
            lp1 += e2 + e3;
            __nv_bfloat162 q01 = __floats2bfloat162_rn(e0, e1);
            __nv_bfloat162 q23 = __floats2bfloat162_rn(e2, e3);
            *reinterpret_cast<uint32_t*>(Eg + (size_t)(wq + g) * TK + c) =
                *reinterpret_cast<uint32_t*>(&q01);
            *reinterpret_cast<uint32_t*>(Eg + (size_t)(wq + g + 8) * TK + c) =
                *reinterpret_cast<uint32_t*>(&q23);
            // D->A: lane needs cols {tg, tg+4} of this 8-col block
            const float x0 = __shfl_sync(0xffffffffu, e0, src1);
            const float x1 = __shfl_sync(0xffffffffu, e1, src1);
            const float x2 = __shfl_sync(0xffffffffu, e2, src1);
            const float x3 = __shfl_sync(0xffffffffu, e3, src1);
            const float y0 = __shfl_sync(0xffffffffu, e0, src2);
            const float y1 = __shfl_sync(0xffffffffu, e1, src2);
            const float y2 = __shfl_sync(0xffffffffu, e2, src2);
            const float y3 = __shfl_sync(0xffffffffu, e3, src2);
            s[nt][0] = tf32f(odd ? x1 : x0);   // P[r][tg]
            s[nt][1] = tf32f(odd ? x3 : x2);   // P[r+8][tg]
            s[nt][2] = tf32f(odd ? y1 : y0);   // P[r][tg+4]
            s[nt][3] = tf32f(odd ? y3 : y2);   // P[r+8][tg+4]
        }

        // O += P V : A-frags = s[kk], B-frags from Vt[dv][k]
#pragma unroll
        for (int kk = 0; kk < 8; ++kk) {
            const int k0 = kk * 8;
            const uint32_t a0 = __float_as_uint(s[kk][0]);
            const uint32_t a1 = __float_as_uint(s[kk][1]);
            const uint32_t a2 = __float_as_uint(s[kk][2]);
            const uint32_t a3 = __float_as_uint(s[kk][3]);
#pragma unroll
            for (int nt = 0; nt < 8; ++nt) {
                const uint32_t b0 =
                    __float_as_uint(Vt[(nt * 8 + g) * 68 + k0 + tg]);
                const uint32_t b1 =
                    __float_as_uint(Vt[(nt * 8 + g) * 68 + k0 + 4 + tg]);
                MMA_TF32(accO[nt], a0, a1, a2, a3, b0, b1);
            }
        }
    }

    // row-sum reduction across the quad lanes (tg), then smem atomics
    lp0 += __shfl_xor_sync(0xffffffffu, lp0, 1);
    lp0 += __shfl_xor_sync(0xffffffffu, lp0, 2);
    lp1 += __shfl_xor_sync(0xffffffffu, lp1, 1);
    lp1 += __shfl_xor_sync(0xffffffffu, lp1, 2);
    if (tg == 0) {
        atomicAdd(&ls[wq + g], lp0);
        atomicAdd(&ls[wq + g + 8], lp1);
    }
    __syncthreads();

    const float inv0 = 1.f / ls[wq + g];
    const float inv1 = 1.f / ls[wq + g + 8];
    float* Og = g_O + ((size_t)(b * TQ + qt * 128)) * D_MODEL + h * HD;
#pragma unroll
    for (int nt = 0; nt < 8; ++nt) {
        const int c = nt * 8 + 2 * tg;
        float2 o0, o1;
        o0.x = accO[nt][0] * inv0; o0.y = accO[nt][1] * inv0;
        o1.x = accO[nt][2] * inv1; o1.y = accO[nt][3] * inv1;
        *(float2*)(Og + (size_t)(wq + g) * D_MODEL + c) = o0;
        *(float2*)(Og + (size_t)(wq + g + 8) * D_MODEL + c) = o1;
    }
    if (tid < 128)
        g_L[((size_t)b * NHEAD + h) * TQ + qt * 128 + tid] = ls[tid];
}

// ---------------------------------------------------------------------------
// Coverage reduction: covout[b,k] += sum_{h,q} E[b,h,q,k] / (16 * l[b,h,q])
// ---------------------------------------------------------------------------
__global__ __launch_bounds__(256) void cov_reduce_kernel(float* __restrict__ covout)
{
    __shared__ float il[128];
    const int qc = blockIdx.x, h = blockIdx.y, b = blockIdx.z;
    const int tid = threadIdx.x;
    if (tid < 128)
        il[tid] = 1.f / (16.f * g_L[((size_t)b * NHEAD + h) * TQ + qc * 128 + tid]);
    __syncthreads();

    const __nv_bfloat16* E = g_E +
        ((size_t)(b * NHEAD + h) * TQ + qc * 128) * TK;
    const int k0 = tid * 4;
    float a0 = 0.f, a1 = 0.f, a2 = 0.f, a3 = 0.f;
#pragma unroll 4
    for (int q = 0; q < 128; ++q) {
        uint2 p = *reinterpret_cast<const uint2*>(E + (size_t)q * TK + k0);
        const float wq = il[q];
        __nv_bfloat162 lo = *reinterpret_cast<__nv_bfloat162*>(&p.x);
        __nv_bfloat162 hi = *reinterpret_cast<__nv_bfloat162*>(&p.y);
        a0 = fmaf(__bfloat162float(lo.x), wq, a0);
        a1 = fmaf(__bfloat162float(lo.y), wq, a1);
        a2 = fmaf(__bfloat162float(hi.x), wq, a2);
        a3 = fmaf(__bfloat162float(hi.y), wq, a3);
    }
    atomicAdd(&covout[b * TK + k0 + 0], a0);
    atomicAdd(&covout[b * TK + k0 + 1], a1);
    atomicAdd(&covout[b * TK + k0 + 2], a2);
    atomicAdd(&covout[b * TK + k0 + 3], a3);
}

__global__ void cov_init_kernel(const float* __restrict__ coverage,
                                float* __restrict__ covout)
{
    int i = blockIdx.x * blockDim.x + threadIdx.x;
    if (i < BATCH * TK) covout[i] = coverage[i];
}

// ---------------------------------------------------------------------------
extern "C" void kernel_launch(void* const* d_in, const int* in_sizes, int n_in,
                              void* d_out, int out_size)
{
    const float* query    = (const float*)d_in[0];
    const float* memory   = (const float*)d_in[1];
    const float* coverage = (const float*)d_in[2];
    const float* Wq = (const float*)d_in[3];
    const float* bq = (const float*)d_in[4];
    const float* Wk = (const float*)d_in[5];
    const float* bk = (const float*)d_in[6];
    const float* Wv = (const float*)d_in[7];
    const float* bv = (const float*)d_in[8];
    const float* Wo = (const float*)d_in[9];
    const float* bo = (const float*)d_in[10];
    const float* Wcov = (const float*)d_in[11];

    float* out = (float*)d_out;
    float* covout = out + (size_t)BATCH * TQ * D_MODEL;

    float *Qp, *Kp, *Vp, *Op;
    cudaGetSymbolAddress((void**)&Qp, g_Q);
    cudaGetSymbolAddress((void**)&Kp, g_K);
    cudaGetSymbolAddress((void**)&Vp, g_V);
    cudaGetSymbolAddress((void**)&Op, g_O);

    const int M = BATCH * TQ;   // 8192
    const dim3 ggrid(D_MODEL / 128, M / 128);

    cudaFuncSetAttribute(gemm_mma_kernel, cudaFuncAttributeMaxDynamicSharedMemorySize,
                         GEMM_DSMEM);
    cudaFuncSetAttribute(attn_mma_kernel, cudaFuncAttributeMaxDynamicSharedMemorySize,
                         ATTN3_DSMEM);

    gemm_mma_kernel<<<ggrid, 128, GEMM_DSMEM>>>(query,  Wq, bq, Qp, M, D_MODEL, D_MODEL);
    gemm_mma_kernel<<<ggrid, 128, GEMM_DSMEM>>>(memory, Wk, bk, Kp, M, D_MODEL, D_MODEL);
    gemm_mma_kernel<<<ggrid, 128, GEMM_DSMEM>>>(memory, Wv, bv, Vp, M, D_MODEL, D_MODEL);

    attn_mma_kernel<<<dim3(TQ / 128, NHEAD, BATCH), 256, ATTN3_DSMEM>>>(coverage, Wcov);

    gemm_mma_kernel<<<ggrid, 128, GEMM_DSMEM>>>(Op, Wo, bo, out, M, D_MODEL, D_MODEL);

    cov_init_kernel<<<(BATCH * TK + 255) / 256, 256>>>(coverage, covout);
    cov_reduce_kernel<<<dim3(TQ / 128, NHEAD, BATCH), 256>>>(covout);
}

// round 13
// speedup vs baseline: 1.4319x; 1.4319x over previous
#include <cuda_runtime.h>
#include <cuda_bf16.h>
#include <math.h>
#include <stdint.h>

#define D_MODEL 1024
#define NHEAD 16
#define HD 64
#define BATCH 8
#define TQ 1024
#define TK 1024

// Scratch (static __device__ arrays; no allocation allowed)
__device__ float g_Q[BATCH * TQ * D_MODEL];
__device__ float g_K[BATCH * TK * D_MODEL];
__device__ float g_V[BATCH * TK * D_MODEL];
__device__ float g_O[BATCH * TQ * D_MODEL];
__device__ float g_L[BATCH * NHEAD * TQ];
__device__ __nv_bfloat16 g_E[BATCH * NHEAD * TQ * TK];   // unnormalized exp(scores)

__device__ __forceinline__ uint32_t cvt_tf32(float f) {
    uint32_t o;
    asm("cvt.rna.tf32.f32 %0, %1;" : "=r"(o) : "f"(f));
    return o;
}
__device__ __forceinline__ float tf32f(float f) {
    return __uint_as_float(cvt_tf32(f));
}

#define MMA_TF32(acc, a0, a1, a2, a3, b0, b1)                                   \
    asm volatile(                                                               \
        "mma.sync.aligned.m16n8k8.row.col.f32.tf32.tf32.f32 "                   \
        "{%0,%1,%2,%3}, {%4,%5,%6,%7}, {%8,%9}, {%0,%1,%2,%3};"                 \
        : "+f"((acc)[0]), "+f"((acc)[1]), "+f"((acc)[2]), "+f"((acc)[3])        \
        : "r"(a0), "r"(a1), "r"(a2), "r"(a3), "r"(b0), "r"(b1))

// ---------------------------------------------------------------------------
// mma.sync tf32 GEMM v2:  C[M,N] = A[M,K] @ W[N,K]^T + bias  (row-major)
// CTA tile 128x128, BK=16, 128 threads (4 warps), warp tile 64x64.
// ---------------------------------------------------------------------------
#define GROW 20
#define GSTG (128 * GROW)
#define GEMM_DSMEM (4 * GSTG * 4)

__global__ __launch_bounds__(128) void gemm_mma_kernel(
    const float* __restrict__ A, const float* __restrict__ W,
    const float* __restrict__ bias, float* __restrict__ C,
    int M, int N, int K)
{
    extern __shared__ float smf[];
    const int t = threadIdx.x;
    const int lane = t & 31, w = t >> 5;
    const int bx = blockIdx.x;
    const int by = blockIdx.y;
    const int wm = (w & 1) * 64;
    const int wn = (w >> 1) * 64;
    const int g = lane >> 2, tg = lane & 3;

    const float* Ag = A + (size_t)(by * 128) * K;
    const float* Wg = W + (size_t)(bx * 128) * K;

    float acc[4][8][4];
#pragma unroll
    for (int mt = 0; mt < 4; ++mt)
#pragma unroll
        for (int nt = 0; nt < 8; ++nt)
#pragma unroll
            for (int r = 0; r < 4; ++r) acc[mt][nt][r] = 0.f;

    float4 ra[4], rw[4];
    const int NIT = K / 16;

#pragma unroll
    for (int i = 0; i < 4; ++i) {
        const int idx = t + 128 * i;
        const int r = idx >> 2, fq = idx & 3;
        ra[i] = *(const float4*)(Ag + (size_t)r * K + fq * 4);
        rw[i] = *(const float4*)(Wg + (size_t)r * K + fq * 4);
    }
#pragma unroll
    for (int i = 0; i < 4; ++i) {
        const int idx = t + 128 * i;
        const int r = idx >> 2, fq = idx & 3;
        float4 pa, pb;
        pa.x = tf32f(ra[i].x); pa.y = tf32f(ra[i].y);
        pa.z = tf32f(ra[i].z); pa.w = tf32f(ra[i].w);
        pb.x = tf32f(rw[i].x); pb.y = tf32f(rw[i].y);
        pb.z = tf32f(rw[i].z); pb.w = tf32f(rw[i].w);
        *(float4*)(smf + r * GROW + fq * 4) = pa;
        *(float4*)(smf + 2 * GSTG + r * GROW + fq * 4) = pb;
    }
    __syncthreads();

    for (int it = 0; it < NIT; ++it) {
        const int s = it & 1;
        if (it + 1 < NIT) {
            const int k0 = (it + 1) * 16;
#pragma unroll
            for (int i = 0; i < 4; ++i) {
                const int idx = t + 128 * i;
                const int r = idx >> 2, fq = idx & 3;
                ra[i] = *(const float4*)(Ag + (size_t)r * K + k0 + fq * 4);
                rw[i] = *(const float4*)(Wg + (size_t)r * K + k0 + fq * 4);
            }
        }
        {
            const float* as = smf + s * GSTG;
            const float* ws = smf + 2 * GSTG + s * GSTG;
#pragma unroll
            for (int kk = 0; kk < 2; ++kk) {
                const int k0 = kk * 8;
                uint32_t af[4][4];
#pragma unroll
                for (int mt = 0; mt < 4; ++mt) {
                    const int r0 = wm + mt * 16 + g;
                    af[mt][0] = __float_as_uint(as[r0 * GROW + k0 + tg]);
                    af[mt][1] = __float_as_uint(as[(r0 + 8) * GROW + k0 + tg]);
                    af[mt][2] = __float_as_uint(as[r0 * GROW + k0 + 4 + tg]);
                    af[mt][3] = __float_as_uint(as[(r0 + 8) * GROW + k0 + 4 + tg]);
                }
#pragma unroll
                for (int nt = 0; nt < 8; ++nt) {
                    const int c0 = wn + nt * 8 + g;
                    const uint32_t b0 = __float_as_uint(ws[c0 * GROW + k0 + tg]);
                    const uint32_t b1 = __float_as_uint(ws[c0 * GROW + k0 + 4 + tg]);
#pragma unroll
                    for (int mt = 0; mt < 4; ++mt)
                        MMA_TF32(acc[mt][nt], af[mt][0], af[mt][1], af[mt][2],
                                 af[mt][3], b0, b1);
                }
            }
        }
        if (it + 1 < NIT) {
            float* as = smf + (s ^ 1) * GSTG;
            float* ws = smf + 2 * GSTG + (s ^ 1) * GSTG;
#pragma unroll
            for (int i = 0; i < 4; ++i) {
                const int idx = t + 128 * i;
                const int r = idx >> 2, fq = idx & 3;
                float4 pa, pb;
                pa.x = tf32f(ra[i].x); pa.y = tf32f(ra[i].y);
                pa.z = tf32f(ra[i].z); pa.w = tf32f(ra[i].w);
                pb.x = tf32f(rw[i].x); pb.y = tf32f(rw[i].y);
                pb.z = tf32f(rw[i].z); pb.w = tf32f(rw[i].w);
                *(float4*)(as + r * GROW + fq * 4) = pa;
                *(float4*)(ws + r * GROW + fq * 4) = pb;
            }
        }
        __syncthreads();
    }

#pragma unroll
    for (int mt = 0; mt < 4; ++mt) {
        const int row0 = by * 128 + wm + mt * 16 + g;
#pragma unroll
        for (int nt = 0; nt < 8; ++nt) {
            const int col = bx * 128 + wn + nt * 8 + 2 * tg;
            const float2 b01 = *(const float2*)(bias + col);
            float2 v0, v1;
            v0.x = acc[mt][nt][0] + b01.x;
            v0.y = acc[mt][nt][1] + b01.y;
            v1.x = acc[mt][nt][2] + b01.x;
            v1.y = acc[mt][nt][3] + b01.y;
            *(float2*)(C + (size_t)row0 * N + col) = v0;
            *(float2*)(C + (size_t)(row0 + 8) * N + col) = v1;
        }
    }
}

// ---------------------------------------------------------------------------
// Flash-style attention on mma.sync tf32 (v4).
// CTA = (qtile 128, head, batch), 256 threads = 8 warps; warp owns 16 q rows.
// Q A-fragments held in registers for the whole k-loop. E written to gmem
// straight from registers. P staged via warp-private Ps rows (only a
// __syncwarp between write and read). V staged transposed with an XOR
// column swizzle col = k ^ ((d>>2)&7): PV B-frag loads conflict-free,
// staging stores only 2-way.
// ---------------------------------------------------------------------------
#define ATTN4_SMEM_FLOATS (128 * 68 + 64 * 68 + 64 * 68 + 128 * 68 + 64 + 128)
#define ATTN4_DSMEM (ATTN4_SMEM_FLOATS * 4)

__global__ __launch_bounds__(256, 2) void attn_mma_kernel(
    const float* __restrict__ coverage, const float* __restrict__ Wcov)
{
    extern __shared__ float sm[];
    float* Qs = sm;                   // [q=128][d stride 68]
    float* Ks = Qs + 128 * 68;        // [key=64][d stride 68]
    float* Vt = Ks + 64 * 68;         // [dv=64][key stride 68], XOR-swizzled cols
    float* Ps = Vt + 64 * 68;         // [q=128][key stride 68]
    float* cb = Ps + 128 * 68;        // [64]
    float* ls = cb + 64;              // [128]

    const int qt = blockIdx.x, h = blockIdx.y, b = blockIdx.z;
    const int tid = threadIdx.x;
    const int lane = tid & 31, w = tid >> 5;
    const int g = lane >> 2, tg = lane & 3;
    const int wq = w * 16;
    const float wch = __ldg(&Wcov[h]);

    // Q tile -> smem (tf32), then A-fragments -> registers (kept all k-loop)
    {
        const float* Qg = g_Q + ((size_t)(b * TQ + qt * 128)) * D_MODEL + h * HD;
        for (int i = tid; i < 128 * 16; i += 256) {
            int q = i >> 4, d4 = (i & 15) << 2;
            float4 v = *(const float4*)(Qg + (size_t)q * D_MODEL + d4);
            float4 p;
            p.x = tf32f(v.x); p.y = tf32f(v.y); p.z = tf32f(v.z); p.w = tf32f(v.w);
            *(float4*)(Qs + q * 68 + d4) = p;
        }
    }
    if (tid < 128) ls[tid] = 0.f;
    __syncthreads();

    uint32_t qa[8][4];
#pragma unroll
    for (int kk = 0; kk < 8; ++kk) {
        const int k0 = kk * 8;
        qa[kk][0] = __float_as_uint(Qs[(wq + g) * 68 + k0 + tg]);
        qa[kk][1] = __float_as_uint(Qs[(wq + g + 8) * 68 + k0 + tg]);
        qa[kk][2] = __float_as_uint(Qs[(wq + g) * 68 + k0 + 4 + tg]);
        qa[kk][3] = __float_as_uint(Qs[(wq + g + 8) * 68 + k0 + 4 + tg]);
    }

    float accO[8][4];
#pragma unroll
    for (int nt = 0; nt < 8; ++nt)
#pragma unroll
        for (int r = 0; r < 4; ++r) accO[nt][r] = 0.f;
    float lp0 = 0.f, lp1 = 0.f;

    __nv_bfloat16* Ebase = g_E + (((size_t)(b * NHEAD + h) * TQ + qt * 128)) * TK;

    for (int kt = 0; kt < 16; ++kt) {
        __syncthreads();   // protect Ks/Vt from previous tile's readers
        const float* Kg = g_K + ((size_t)(b * TK + kt * 64)) * D_MODEL + h * HD;
        const float* Vg = g_V + ((size_t)(b * TK + kt * 64)) * D_MODEL + h * HD;
        for (int i = tid; i < 64 * 16; i += 256) {
            int k = i >> 4, d4 = (i & 15) << 2;
            float4 kv = *(const float4*)(Kg + (size_t)k * D_MODEL + d4);
            float4 pk;
            pk.x = tf32f(kv.x); pk.y = tf32f(kv.y);
            pk.z = tf32f(kv.z); pk.w = tf32f(kv.w);
            *(float4*)(Ks + k * 68 + d4) = pk;
            // V transposed + XOR column swizzle: col = k ^ ((d>>2)&7).
            // (d>>2)&7 is constant over the 4 stores of this thread.
            float4 vv = *(const float4*)(Vg + (size_t)k * D_MODEL + d4);
            const int col = k ^ ((d4 >> 2) & 7);
            Vt[(d4 + 0) * 68 + col] = tf32f(vv.x);
            Vt[(d4 + 1) * 68 + col] = tf32f(vv.y);
            Vt[(d4 + 2) * 68 + col] = tf32f(vv.z);
            Vt[(d4 + 3) * 68 + col] = tf32f(vv.w);
        }
        if (tid < 64) cb[tid] = __ldg(&coverage[b * TK + kt * 64 + tid]) * wch;
        __syncthreads();

        // S = Q K^T : warp rows wq..wq+15, 64 key cols (A from registers)
        float s[8][4];
#pragma unroll
        for (int nt = 0; nt < 8; ++nt)
#pragma unroll
            for (int r = 0; r < 4; ++r) s[nt][r] = 0.f;
#pragma unroll
        for (int kk = 0; kk < 8; ++kk) {
            const int k0 = kk * 8;
#pragma unroll
            for (int nt = 0; nt < 8; ++nt) {
                const uint32_t b0 = __float_as_uint(Ks[(nt * 8 + g) * 68 + k0 + tg]);
                const uint32_t b1 = __float_as_uint(Ks[(nt * 8 + g) * 68 + k0 + 4 + tg]);
                MMA_TF32(s[nt], qa[kk][0], qa[kk][1], qa[kk][2], qa[kk][3], b0, b1);
            }
        }

        // exp + bias -> Ps (warp-private rows) + E gmem from registers
        __nv_bfloat16* Eg = Ebase + kt * 64;
#pragma unroll
        for (int nt = 0; nt < 8; ++nt) {
            const int c = nt * 8 + 2 * tg;
            const float cb0 = cb[c], cb1 = cb[c + 1];
            const float e0 = __expf(fmaf(s[nt][0], 0.125f, cb0));
            const float e1 = __expf(fmaf(s[nt][1], 0.125f, cb1));
            const float e2 = __expf(fmaf(s[nt][2], 0.125f, cb0));
            const float e3 = __expf(fmaf(s[nt][3], 0.125f, cb1));
            lp0 += e0 + e1;
            lp1 += e2 + e3;
            float2 p0, p1;
            p0.x = tf32f(e0); p0.y = tf32f(e1);
            p1.x = tf32f(e2); p1.y = tf32f(e3);
            *(float2*)(Ps + (wq + g) * 68 + c) = p0;
            *(float2*)(Ps + (wq + g + 8) * 68 + c) = p1;
            __nv_bfloat162 q01 = __floats2bfloat162_rn(e0, e1);
            __nv_bfloat162 q23 = __floats2bfloat162_rn(e2, e3);
            *reinterpret_cast<uint32_t*>(Eg + (size_t)(wq + g) * TK + c) =
                *reinterpret_cast<uint32_t*>(&q01);
            *reinterpret_cast<uint32_t*>(Eg + (size_t)(wq + g + 8) * TK + c) =
                *reinterpret_cast<uint32_t*>(&q23);
        }
        __syncwarp();   // Ps rows are warp-private: warp-level ordering suffices

        // O += P V : A from Ps (conflict-free), B from swizzled Vt
#pragma unroll
        for (int kk = 0; kk < 8; ++kk) {
            const int k0 = kk * 8;
            const uint32_t a0 = __float_as_uint(Ps[(wq + g) * 68 + k0 + tg]);
            const uint32_t a1 = __float_as_uint(Ps[(wq + g + 8) * 68 + k0 + tg]);
            const uint32_t a2 = __float_as_uint(Ps[(wq + g) * 68 + k0 + 4 + tg]);
            const uint32_t a3 = __float_as_uint(Ps[(wq + g + 8) * 68 + k0 + 4 + tg]);
#pragma unroll
            for (int nt = 0; nt < 8; ++nt) {
                const int d = nt * 8 + g;
                const int A = (2 * nt + (g >> 2)) & 7;
                const int col0 = (k0 + tg) ^ A;
                const uint32_t b0 = __float_as_uint(Vt[d * 68 + col0]);
                const uint32_t b1 = __float_as_uint(Vt[d * 68 + (col0 ^ 4)]);
                MMA_TF32(accO[nt], a0, a1, a2, a3, b0, b1);
            }
        }
    }

    // row-sum reduction across the quad lanes (tg), then smem atomics
    lp0 += __shfl_xor_sync(0xffffffffu, lp0, 1);
    lp0 += __shfl_xor_sync(0xffffffffu, lp0, 2);
    lp1 += __shfl_xor_sync(0xffffffffu, lp1, 1);
    lp1 += __shfl_xor_sync(0xffffffffu, lp1, 2);
    if (tg == 0) {
        atomicAdd(&ls[wq + g], lp0);
        atomicAdd(&ls[wq + g + 8], lp1);
    }
    __syncthreads();

    const float inv0 = 1.f / ls[wq + g];
    const float inv1 = 1.f / ls[wq + g + 8];
    float* Og = g_O + ((size_t)(b * TQ + qt * 128)) * D_MODEL + h * HD;
#pragma unroll
    for (int nt = 0; nt < 8; ++nt) {
        const int c = nt * 8 + 2 * tg;
        float2 o0, o1;
        o0.x = accO[nt][0] * inv0; o0.y = accO[nt][1] * inv0;
        o1.x = accO[nt][2] * inv1; o1.y = accO[nt][3] * inv1;
        *(float2*)(Og + (size_t)(wq + g) * D_MODEL + c) = o0;
        *(float2*)(Og + (size_t)(wq + g + 8) * D_MODEL + c) = o1;
    }
    if (tid < 128)
        g_L[((size_t)b * NHEAD + h) * TQ + qt * 128 + tid] = ls[tid];
}

// ---------------------------------------------------------------------------
// Coverage reduction: covout[b,k] += sum_{h,q} E[b,h,q,k] / (16 * l[b,h,q])
// ---------------------------------------------------------------------------
__global__ __launch_bounds__(256) void cov_reduce_kernel(float* __restrict__ covout)
{
    __shared__ float il[128];
    const int qc = blockIdx.x, h = blockIdx.y, b = blockIdx.z;
    const int tid = threadIdx.x;
    if (tid < 128)
        il[tid] = 1.f / (16.f * g_L[((size_t)b * NHEAD + h) * TQ + qc * 128 + tid]);
    __syncthreads();

    const __nv_bfloat16* E = g_E +
        ((size_t)(b * NHEAD + h) * TQ + qc * 128) * TK;
    const int k0 = tid * 4;
    float a0 = 0.f, a1 = 0.f, a2 = 0.f, a3 = 0.f;
#pragma unroll 4
    for (int q = 0; q < 128; ++q) {
        uint2 p = *reinterpret_cast<const uint2*>(E + (size_t)q * TK + k0);
        const float wq = il[q];
        __nv_bfloat162 lo = *reinterpret_cast<__nv_bfloat162*>(&p.x);
        __nv_bfloat162 hi = *reinterpret_cast<__nv_bfloat162*>(&p.y);
        a0 = fmaf(__bfloat162float(lo.x), wq, a0);
        a1 = fmaf(__bfloat162float(lo.y), wq, a1);
        a2 = fmaf(__bfloat162float(hi.x), wq, a2);
        a3 = fmaf(__bfloat162float(hi.y), wq, a3);
    }
    atomicAdd(&covout[b * TK + k0 + 0], a0);
    atomicAdd(&covout[b * TK + k0 + 1], a1);
    atomicAdd(&covout[b * TK + k0 + 2], a2);
    atomicAdd(&covout[b * TK + k0 + 3], a3);
}

__global__ void cov_init_kernel(const float* __restrict__ coverage,
                                float* __restrict__ covout)
{
    int i = blockIdx.x * blockDim.x + threadIdx.x;
    if (i < BATCH * TK) covout[i] = coverage[i];
}

// ---------------------------------------------------------------------------
extern "C" void kernel_launch(void* const* d_in, const int* in_sizes, int n_in,
                              void* d_out, int out_size)
{
    const float* query    = (const float*)d_in[0];
    const float* memory   = (const float*)d_in[1];
    const float* coverage = (const float*)d_in[2];
    const float* Wq = (const float*)d_in[3];
    const float* bq = (const float*)d_in[4];
    const float* Wk = (const float*)d_in[5];
    const float* bk = (const float*)d_in[6];
    const float* Wv = (const float*)d_in[7];
    const float* bv = (const float*)d_in[8];
    const float* Wo = (const float*)d_in[9];
    const float* bo = (const float*)d_in[10];
    const float* Wcov = (const float*)d_in[11];

    float* out = (float*)d_out;
    float* covout = out + (size_t)BATCH * TQ * D_MODEL;

    float *Qp, *Kp, *Vp, *Op;
    cudaGetSymbolAddress((void**)&Qp, g_Q);
    cudaGetSymbolAddress((void**)&Kp, g_K);
    cudaGetSymbolAddress((void**)&Vp, g_V);
    cudaGetSymbolAddress((void**)&Op, g_O);

    const int M = BATCH * TQ;   // 8192
    const dim3 ggrid(D_MODEL / 128, M / 128);

    cudaFuncSetAttribute(gemm_mma_kernel, cudaFuncAttributeMaxDynamicSharedMemorySize,
                         GEMM_DSMEM);
    cudaFuncSetAttribute(attn_mma_kernel, cudaFuncAttributeMaxDynamicSharedMemorySize,
                         ATTN4_DSMEM);

    gemm_mma_kernel<<<ggrid, 128, GEMM_DSMEM>>>(query,  Wq, bq, Qp, M, D_MODEL, D_MODEL);
    gemm_mma_kernel<<<ggrid, 128, GEMM_DSMEM>>>(memory, Wk, bk, Kp, M, D_MODEL, D_MODEL);
    gemm_mma_kernel<<<ggrid, 128, GEMM_DSMEM>>>(memory, Wv, bv, Vp, M, D_MODEL, D_MODEL);

    attn_mma_kernel<<<dim3(TQ / 128, NHEAD, BATCH), 256, ATTN4_DSMEM>>>(coverage, Wcov);

    gemm_mma_kernel<<<ggrid, 128, GEMM_DSMEM>>>(Op, Wo, bo, out, M, D_MODEL, D_MODEL);

    cov_init_kernel<<<(BATCH * TK + 255) / 256, 256>>>(coverage, covout);
    cov_reduce_kernel<<<dim3(TQ / 128, NHEAD, BATCH), 256>>>(covout);
}